// round 8
// baseline (speedup 1.0000x reference)
#include <cuda_runtime.h>
#include <cstdint>

#define NB 8
#define LQ 256
#define LK 256
#define HH 256
#define DV 256
#define MASK_VALUE -1000000.0f

// Scratch (allocation-free rule: device globals)
__device__ float g_Qp[NB * LQ * HH];
__device__ float g_Kp[NB * LK * HH];
__device__ float g_S[NB * LQ * LK];
__device__ uint32_t g_Vt[NB * DV * LK];  // V transposed, pre-converted to tf32: [b][d][k]

__device__ __forceinline__ float tanh_fast(float x) {
    float y;
    asm("tanh.approx.f32 %0, %1;" : "=f"(y) : "f"(x));
    return y;
}

__device__ __forceinline__ uint32_t f2tf(float x) {
    uint32_t r;
    asm("cvt.rna.tf32.f32 %0, %1;" : "=r"(r) : "f"(x));
    return r;
}

__device__ __forceinline__ uint4 tf4(float4 v) {
    return make_uint4(f2tf(v.x), f2tf(v.y), f2tf(v.z), f2tf(v.w));
}

// D += A(16x8,row) * B(8x8,col)  in tf32, fp32 accum
__device__ __forceinline__ void mma8(float* d, const uint32_t* a, const uint32_t* b) {
    asm("mma.sync.aligned.m16n8k8.row.col.f32.tf32.tf32.f32 "
        "{%0,%1,%2,%3}, {%4,%5,%6,%7}, {%8,%9}, {%0,%1,%2,%3};"
        : "+f"(d[0]), "+f"(d[1]), "+f"(d[2]), "+f"(d[3])
        : "r"(a[0]), "r"(a[1]), "r"(a[2]), "r"(a[3]), "r"(b[0]), "r"(b[1]));
}

#define FS 260                       // full-K smem stride: 260 % 32 == 4 -> conflict-free
#define SMEM_BYTES (2 * 32 * FS * 4) // 66560

extern __shared__ uint32_t smem_u32[];

// ---------------------------------------------------------------------------
// proj_kernel, grid (8, 64, 3), 128 threads, dynamic smem:
//   z=0: g_Qp = queries @ W_q^T        (NT GEMM, tf32 MMA, single sync)
//   z=1: g_Kp = keyes   @ W_k^T
//   z=2: g_Vt[b][d][k] = tf32(V[b][k][d])   (transpose, 512 blocks)
// GEMM: CTA 32m x 32n, 4 warps, warp tile 16x16, K=256 staged fully in smem.
// ---------------------------------------------------------------------------
__global__ void __launch_bounds__(128) proj_kernel(
    const float* __restrict__ Xq, const float* __restrict__ Wq,
    const float* __restrict__ Xk, const float* __restrict__ Wk,
    const float* __restrict__ Vv) {
    const int tid = threadIdx.x;

    if (blockIdx.z == 2) {
        // ---- V transpose: one 32x32 tile per block ----
        const int t = blockIdx.y * 8 + blockIdx.x;   // 0..511
        const int b = t >> 6;
        const int r = t & 63;
        const int k0 = (r >> 3) * 32;
        const int d0 = (r & 7) * 32;
        const float* V = Vv + b * LK * DV;
        float* ts = (float*)smem_u32;                // [32 d][33]
        #pragma unroll
        for (int j = 0; j < 2; j++) {
            int i4 = tid + j * 128;                  // 0..255
            int kr = i4 >> 3, c4 = i4 & 7;
            float4 v = *(const float4*)&V[(k0 + kr) * DV + d0 + c4 * 4];
            ts[(c4 * 4 + 0) * 33 + kr] = v.x;
            ts[(c4 * 4 + 1) * 33 + kr] = v.y;
            ts[(c4 * 4 + 2) * 33 + kr] = v.z;
            ts[(c4 * 4 + 3) * 33 + kr] = v.w;
        }
        __syncthreads();
        uint32_t* Vt = g_Vt + b * DV * LK;
        #pragma unroll
        for (int j = 0; j < 2; j++) {
            int i4 = tid + j * 128;
            int dr = i4 >> 3, c4 = i4 & 7;
            const float* p = &ts[dr * 33 + c4 * 4];
            uint4 w = make_uint4(f2tf(p[0]), f2tf(p[1]), f2tf(p[2]), f2tf(p[3]));
            *(uint4*)&Vt[(d0 + dr) * LK + k0 + c4 * 4] = w;
        }
        return;
    }

    // ---- projection GEMM ----
    const float* X;
    const float* W;
    float* C;
    if (blockIdx.z == 0) { X = Xq; W = Wq; C = g_Qp; }
    else                 { X = Xk; W = Wk; C = g_Kp; }

    uint32_t* Xs = smem_u32;            // [32 m][FS]
    uint32_t* Ws = smem_u32 + 32 * FS;  // [32 n][FS]

    const int lane = tid & 31;
    const int warp = tid >> 5;
    const int gid = lane >> 2;
    const int tig = lane & 3;
    const int wm = (warp & 1) * 16;
    const int wn = (warp >> 1) * 16;
    const int m0 = blockIdx.y * 32;
    const int n0 = blockIdx.x * 32;

    // stage full K: 32 rows x 64 float4 each operand; 16 float4 per thread each
    #pragma unroll
    for (int j = 0; j < 16; j++) {
        int idx = tid + j * 128;        // 0..2047
        int row = idx >> 6, c4 = idx & 63;
        uint4 xv = tf4(*(const float4*)&X[(m0 + row) * 256 + c4 * 4]);
        uint4 wv = tf4(*(const float4*)&W[(n0 + row) * 256 + c4 * 4]);
        *(uint4*)&Xs[row * FS + c4 * 4] = xv;
        *(uint4*)&Ws[row * FS + c4 * 4] = wv;
    }
    __syncthreads();

    float d[2][4] = {};
    #pragma unroll
    for (int ks = 0; ks < 32; ks++) {
        const int kk = ks * 8;
        uint32_t a[4], b0[2], b1[2];
        const int rr = wm + gid;
        a[0] = Xs[rr * FS + kk + tig];
        a[1] = Xs[(rr + 8) * FS + kk + tig];
        a[2] = Xs[rr * FS + kk + tig + 4];
        a[3] = Xs[(rr + 8) * FS + kk + tig + 4];
        const int nn = wn + gid;
        b0[0] = Ws[nn * FS + kk + tig];
        b0[1] = Ws[nn * FS + kk + tig + 4];
        b1[0] = Ws[(nn + 8) * FS + kk + tig];
        b1[1] = Ws[(nn + 8) * FS + kk + tig + 4];
        mma8(d[0], a, b0);
        mma8(d[1], a, b1);
    }

    const int row = m0 + wm + gid;
    #pragma unroll
    for (int jn = 0; jn < 2; jn++) {
        const int col = n0 + wn + jn * 8 + tig * 2;
        *(float2*)&C[row * 256 + col] = make_float2(d[jn][0], d[jn][1]);
        *(float2*)&C[(row + 8) * 256 + col] = make_float2(d[jn][2], d[jn][3]);
    }
}

// ---------------------------------------------------------------------------
// Scores: S[b][q][k] = sum_h Wv[h] * tanh(Qp[b][q][h] + Kp[b][k][h]),
// masked to MASK_VALUE where k >= valid_len[b]. Fully-masked 32x32 tiles skip
// all compute. MUFU-bound by design.
// ---------------------------------------------------------------------------
__global__ void scores_kernel(const float* __restrict__ Wv,
                              const int* __restrict__ vlens) {
    const int b = blockIdx.z;
    const int q0 = blockIdx.y * 32;
    const int k0 = blockIdx.x * 32;
    const int tid = threadIdx.x;
    const int tx = tid & 15;
    const int ty = tid >> 4;
    const int vl = vlens[b];
    float* S = g_S + b * LQ * LK;

    if (k0 >= vl) {
        const float2 mv = make_float2(MASK_VALUE, MASK_VALUE);
        #pragma unroll
        for (int i = 0; i < 2; i++)
            *(float2*)&S[(q0 + ty * 2 + i) * LK + k0 + tx * 2] = mv;
        return;
    }

    __shared__ float Qs[64][34];
    __shared__ float Ks[64][34];
    __shared__ float sWv[256];

    sWv[tid] = Wv[tid];

    const float* Qb = g_Qp + (b * LQ + q0) * HH;
    const float* Kb = g_Kp + (b * LK + k0) * HH;

    float a00 = 0.f, a01 = 0.f, a10 = 0.f, a11 = 0.f;

    for (int h0 = 0; h0 < HH; h0 += 64) {
        #pragma unroll
        for (int idx = tid; idx < 32 * 64; idx += 256) {
            int r = idx >> 6;
            int h = idx & 63;
            Qs[h][r] = Qb[r * HH + h0 + h];
            Ks[h][r] = Kb[r * HH + h0 + h];
        }
        __syncthreads();
        #pragma unroll 8
        for (int h = 0; h < 64; h++) {
            float2 qv = *(const float2*)&Qs[h][ty * 2];
            float2 kv = *(const float2*)&Ks[h][tx * 2];
            float wv = sWv[h0 + h];
            a00 += wv * tanh_fast(qv.x + kv.x);
            a01 += wv * tanh_fast(qv.x + kv.y);
            a10 += wv * tanh_fast(qv.y + kv.x);
            a11 += wv * tanh_fast(qv.y + kv.y);
        }
        __syncthreads();
    }

    const int kA = k0 + tx * 2;
    const int kB = kA + 1;
    const int qA = q0 + ty * 2;
    const int qB = qA + 1;
    S[qA * LK + kA] = (kA < vl) ? a00 : MASK_VALUE;
    S[qA * LK + kB] = (kB < vl) ? a01 : MASK_VALUE;
    S[qB * LK + kA] = (kA < vl) ? a10 : MASK_VALUE;
    S[qB * LK + kB] = (kB < vl) ? a11 : MASK_VALUE;
}

// ---------------------------------------------------------------------------
// Softmax over axis=1 (QUERY axis) per (b, k) column — reference quirk.
// ---------------------------------------------------------------------------
__global__ void softmax_kernel() {
    const int b = blockIdx.y;
    const int tx = threadIdx.x & 31;
    const int ty = threadIdx.x >> 5;  // 0..7
    const int k = blockIdx.x * 32 + tx;
    float* S = g_S + b * LQ * LK;

    float vals[32];
    float m = -3.4e38f;
    #pragma unroll
    for (int i = 0; i < 32; i++) {
        vals[i] = S[(i * 8 + ty) * LK + k];
        m = fmaxf(m, vals[i]);
    }

    __shared__ float red[8][33];
    red[ty][tx] = m;
    __syncthreads();
    float M = red[0][tx];
    #pragma unroll
    for (int t = 1; t < 8; t++) M = fmaxf(M, red[t][tx]);
    __syncthreads();

    float s = 0.f;
    #pragma unroll
    for (int i = 0; i < 32; i++) {
        vals[i] = __expf(vals[i] - M);
        s += vals[i];
    }
    red[ty][tx] = s;
    __syncthreads();
    float SUM = 0.f;
    #pragma unroll
    for (int t = 0; t < 8; t++) SUM += red[t][tx];

    const float inv = 1.0f / SUM;
    #pragma unroll
    for (int i = 0; i < 32; i++)
        S[(i * 8 + ty) * LK + k] = vals[i] * inv;
}

// ---------------------------------------------------------------------------
// Output NN GEMM (tf32): out[b][q][d] = sum_k A[b][q][k]*Vt[b][d][k]
// CTA 32q x 32d, 128 threads, warp tile 16x16; full-K staged once, one sync.
// Vt is already transposed + tf32 so staging is pure uint4 copies.
// grid (8, 8, 8) = 512 blocks.
// ---------------------------------------------------------------------------
__global__ void __launch_bounds__(128) out_kernel(float* __restrict__ out) {
    const int b = blockIdx.z;
    const int q0 = blockIdx.y * 32;
    const int d0 = blockIdx.x * 32;
    const int tid = threadIdx.x;
    const int lane = tid & 31;
    const int warp = tid >> 5;
    const int gid = lane >> 2;
    const int tig = lane & 3;
    const int wq = (warp & 1) * 16;
    const int wn = (warp >> 1) * 16;

    const float* A = g_S + b * LQ * LK;
    const uint32_t* Vt = g_Vt + b * DV * LK;

    uint32_t* As = smem_u32;            // [32 q][FS]
    uint32_t* Vs = smem_u32 + 32 * FS;  // [32 d][FS]

    #pragma unroll
    for (int j = 0; j < 16; j++) {
        int idx = tid + j * 128;
        int row = idx >> 6, c4 = idx & 63;
        uint4 av = tf4(*(const float4*)&A[(q0 + row) * LK + c4 * 4]);
        uint4 vv = *(const uint4*)&Vt[(d0 + row) * LK + c4 * 4];
        *(uint4*)&As[row * FS + c4 * 4] = av;
        *(uint4*)&Vs[row * FS + c4 * 4] = vv;
    }
    __syncthreads();

    float d[2][4] = {};
    #pragma unroll
    for (int ks = 0; ks < 32; ks++) {
        const int kk = ks * 8;
        uint32_t a[4], b0[2], b1[2];
        const int rr = wq + gid;
        a[0] = As[rr * FS + kk + tig];
        a[1] = As[(rr + 8) * FS + kk + tig];
        a[2] = As[rr * FS + kk + tig + 4];
        a[3] = As[(rr + 8) * FS + kk + tig + 4];
        const int nn = wn + gid;
        b0[0] = Vs[nn * FS + kk + tig];
        b0[1] = Vs[nn * FS + kk + tig + 4];
        b1[0] = Vs[(nn + 8) * FS + kk + tig];
        b1[1] = Vs[(nn + 8) * FS + kk + tig + 4];
        mma8(d[0], a, b0);
        mma8(d[1], a, b1);
    }

    float* O = out + b * LQ * DV;
    const int row = q0 + wq + gid;
    #pragma unroll
    for (int jn = 0; jn < 2; jn++) {
        const int col = d0 + wn + jn * 8 + tig * 2;
        *(float2*)&O[row * DV + col] = make_float2(d[jn][0], d[jn][1]);
        *(float2*)&O[(row + 8) * DV + col] = make_float2(d[jn][2], d[jn][3]);
    }
}

extern "C" void kernel_launch(void* const* d_in, const int* in_sizes, int n_in,
                              void* d_out, int out_size) {
    const float* queries    = (const float*)d_in[0];
    const float* keyes      = (const float*)d_in[1];
    const float* values     = (const float*)d_in[2];
    const int*   valid_lens = (const int*)d_in[3];
    const float* W_q        = (const float*)d_in[4];
    const float* W_k        = (const float*)d_in[5];
    const float* W_v        = (const float*)d_in[6];
    float* out = (float*)d_out;

    static bool attr_set = false;
    if (!attr_set) {
        cudaFuncSetAttribute(proj_kernel, cudaFuncAttributeMaxDynamicSharedMemorySize, SMEM_BYTES);
        cudaFuncSetAttribute(out_kernel, cudaFuncAttributeMaxDynamicSharedMemorySize, SMEM_BYTES);
        attr_set = true;
    }

    proj_kernel<<<dim3(8, 64, 3), 128, SMEM_BYTES>>>(queries, W_q, keyes, W_k, values);
    scores_kernel<<<dim3(8, 8, 8), 256>>>(W_v, valid_lens);
    softmax_kernel<<<dim3(8, 8), 256>>>();
    out_kernel<<<dim3(8, 8, 8), 128, SMEM_BYTES>>>(out);
}

// round 9
// speedup vs baseline: 1.1080x; 1.1080x over previous
#include <cuda_runtime.h>
#include <cuda_fp16.h>
#include <cstdint>

#define NB 8
#define LQ 256
#define LK 256
#define HH 256
#define DV 256
#define MASK_VALUE -1000000.0f

// Scratch (allocation-free rule: device globals)
__device__ float g_Qp[NB * LQ * HH];
__device__ float g_Kp[NB * LK * HH];
__device__ float g_S[NB * LQ * LK];

__device__ __forceinline__ uint32_t f2tf(float x) {
    uint32_t r;
    asm("cvt.rna.tf32.f32 %0, %1;" : "=r"(r) : "f"(x));
    return r;
}

__device__ __forceinline__ __half2 tanh2(__half2 x) {
    uint32_t xi = *(uint32_t*)&x;
    uint32_t yi;
    asm("tanh.approx.f16x2 %0, %1;" : "=r"(yi) : "r"(xi));
    return *(__half2*)&yi;
}

// D += A(16x8,row) * B(8x8,col)  in tf32, fp32 accum
__device__ __forceinline__ void mma8(float* d, const uint32_t* a, const uint32_t* b) {
    asm("mma.sync.aligned.m16n8k8.row.col.f32.tf32.tf32.f32 "
        "{%0,%1,%2,%3}, {%4,%5,%6,%7}, {%8,%9}, {%0,%1,%2,%3};"
        : "+f"(d[0]), "+f"(d[1]), "+f"(d[2]), "+f"(d[3])
        : "r"(a[0]), "r"(a[1]), "r"(a[2]), "r"(a[3]), "r"(b[0]), "r"(b[1]));
}

#define TS 36  // smem stride, k-contiguous tiles (fragment LDS conflict-free)
#define VS 35  // smem stride, transposed V tile (<=2-way)

// ---------------------------------------------------------------------------
// Projection NT GEMM (tf32, R5 structure): C[m][n] = sum_k X[m][k]*W[n][k]
// CTA 64m x 64n, 4 warps (2x2) of 32x32 warp tiles; kc=32, double-buffered.
// grid (4, 32, 2) = 256 blocks.
// ---------------------------------------------------------------------------
__global__ void __launch_bounds__(128) proj_kernel(
    const float* __restrict__ Xq, const float* __restrict__ Wq,
    const float* __restrict__ Xk, const float* __restrict__ Wk) {
    const float* X;
    const float* W;
    float* C;
    if (blockIdx.z == 0) { X = Xq; W = Wq; C = g_Qp; }
    else                 { X = Xk; W = Wk; C = g_Kp; }

    __shared__ uint32_t Xs[2][64 * TS];
    __shared__ uint32_t Ws[2][64 * TS];

    const int tid = threadIdx.x;
    const int lane = tid & 31;
    const int warp = tid >> 5;
    const int gid = lane >> 2;   // 0..7
    const int tig = lane & 3;    // 0..3
    const int wm = (warp & 1) * 32;
    const int wn = (warp >> 1) * 32;
    const int m0 = blockIdx.y * 64;
    const int n0 = blockIdx.x * 64;

    int srow[4], sc4[4];
    #pragma unroll
    for (int j = 0; j < 4; j++) {
        int idx = tid + j * 128;
        srow[j] = idx >> 3;   // 0..63
        sc4[j]  = idx & 7;    // 0..7
    }

    float d[2][4][4];
    #pragma unroll
    for (int i = 0; i < 2; i++)
        #pragma unroll
        for (int j = 0; j < 4; j++)
            #pragma unroll
            for (int e = 0; e < 4; e++) d[i][j][e] = 0.f;

    float4 xv[4], wv[4];
    #pragma unroll
    for (int j = 0; j < 4; j++) {
        xv[j] = *(const float4*)&X[(m0 + srow[j]) * 256 + sc4[j] * 4];
        wv[j] = *(const float4*)&W[(n0 + srow[j]) * 256 + sc4[j] * 4];
    }

    for (int c = 0; c < 8; c++) {
        uint32_t* XB = Xs[c & 1];
        uint32_t* WB = Ws[c & 1];
        #pragma unroll
        for (int j = 0; j < 4; j++) {
            uint32_t* px = &XB[srow[j] * TS + sc4[j] * 4];
            px[0] = f2tf(xv[j].x); px[1] = f2tf(xv[j].y);
            px[2] = f2tf(xv[j].z); px[3] = f2tf(xv[j].w);
            uint32_t* pw = &WB[srow[j] * TS + sc4[j] * 4];
            pw[0] = f2tf(wv[j].x); pw[1] = f2tf(wv[j].y);
            pw[2] = f2tf(wv[j].z); pw[3] = f2tf(wv[j].w);
        }
        __syncthreads();

        if (c < 7) {
            const int k0 = (c + 1) * 32;
            #pragma unroll
            for (int j = 0; j < 4; j++) {
                xv[j] = *(const float4*)&X[(m0 + srow[j]) * 256 + k0 + sc4[j] * 4];
                wv[j] = *(const float4*)&W[(n0 + srow[j]) * 256 + k0 + sc4[j] * 4];
            }
        }

        #pragma unroll
        for (int ks = 0; ks < 4; ks++) {
            const int kk = ks * 8;
            uint32_t a[2][4], b[4][2];
            #pragma unroll
            for (int i = 0; i < 2; i++) {
                int r = wm + i * 16 + gid;
                a[i][0] = XB[r * TS + kk + tig];
                a[i][1] = XB[(r + 8) * TS + kk + tig];
                a[i][2] = XB[r * TS + kk + tig + 4];
                a[i][3] = XB[(r + 8) * TS + kk + tig + 4];
            }
            #pragma unroll
            for (int jn = 0; jn < 4; jn++) {
                int n = wn + jn * 8 + gid;
                b[jn][0] = WB[n * TS + kk + tig];
                b[jn][1] = WB[n * TS + kk + tig + 4];
            }
            #pragma unroll
            for (int i = 0; i < 2; i++)
                #pragma unroll
                for (int jn = 0; jn < 4; jn++) mma8(d[i][jn], a[i], b[jn]);
        }
    }

    #pragma unroll
    for (int i = 0; i < 2; i++)
        #pragma unroll
        for (int jn = 0; jn < 4; jn++) {
            int row = m0 + wm + i * 16 + gid;
            int col = n0 + wn + jn * 8 + tig * 2;
            *(float2*)&C[row * 256 + col] = make_float2(d[i][jn][0], d[i][jn][1]);
            *(float2*)&C[(row + 8) * 256 + col] = make_float2(d[i][jn][2], d[i][jn][3]);
        }
}

// ---------------------------------------------------------------------------
// Scores (fp16x2 tanh): S[b][q][k] = sum_h Wv[h]*tanh(Qp[b][q][h]+Kp[b][k][h])
// K packed in half2 pairs, Q duplicated in half2: one MUFU.TANH.f16x2 does
// two tanh. Accumulation stays fp32. Masked 32x32 tiles skip all compute.
// ---------------------------------------------------------------------------
__global__ void scores_kernel(const float* __restrict__ Wv,
                              const int* __restrict__ vlens) {
    const int b = blockIdx.z;
    const int q0 = blockIdx.y * 32;
    const int k0 = blockIdx.x * 32;
    const int tid = threadIdx.x;
    const int tx = tid & 15;    // k-pair index: k = k0 + 2*tx + {0,1}
    const int ty = tid >> 4;    // q: q0 + 2*ty + {0,1}
    const int vl = vlens[b];
    float* S = g_S + b * LQ * LK;

    if (k0 >= vl) {
        const float2 mv = make_float2(MASK_VALUE, MASK_VALUE);
        #pragma unroll
        for (int i = 0; i < 2; i++)
            *(float2*)&S[(q0 + 2 * ty + i) * LK + k0 + 2 * tx] = mv;
        return;
    }

    __shared__ __half2 Qs[64][34];  // dup(q) per (h, q)
    __shared__ __half2 Ks[64][18];  // (k0,k1) pair per (h, kpair)
    __shared__ float sWv[256];

    sWv[tid] = Wv[tid];

    const float* Qb = g_Qp + (b * LQ + q0) * HH;
    const float* Kb = g_Kp + (b * LK + k0) * HH;

    float a00 = 0.f, a01 = 0.f, a10 = 0.f, a11 = 0.f;

    for (int h0 = 0; h0 < HH; h0 += 64) {
        // stage Q dup: 64 h x 32 q = 2048 entries, 8 per thread
        #pragma unroll
        for (int j = 0; j < 8; j++) {
            int idx = tid + j * 256;
            int h = idx & 63;
            int qi = idx >> 6;          // 0..31
            float q = Qb[qi * HH + h0 + h];
            Qs[h][qi] = __float2half2_rn(q);
        }
        // stage K pairs: 64 h x 16 pairs = 1024 entries, 4 per thread
        #pragma unroll
        for (int j = 0; j < 4; j++) {
            int idx = tid + j * 256;
            int h = idx & 63;
            int kj = idx >> 6;          // 0..15
            float ka = Kb[(2 * kj) * HH + h0 + h];
            float kb2 = Kb[(2 * kj + 1) * HH + h0 + h];
            Ks[h][kj] = __floats2half2_rn(ka, kb2);
        }
        __syncthreads();
        #pragma unroll 8
        for (int h = 0; h < 64; h++) {
            __half2 kp = Ks[h][tx];
            __half2 s0 = __hadd2(Qs[h][2 * ty], kp);
            __half2 s1 = __hadd2(Qs[h][2 * ty + 1], kp);
            float2 f0 = __half22float2(tanh2(s0));
            float2 f1 = __half22float2(tanh2(s1));
            float wv = sWv[h0 + h];
            a00 += wv * f0.x;
            a01 += wv * f0.y;
            a10 += wv * f1.x;
            a11 += wv * f1.y;
        }
        __syncthreads();
    }

    const int kA = k0 + 2 * tx;
    const int kB = kA + 1;
    const int qA = q0 + 2 * ty;
    const int qB = qA + 1;
    S[qA * LK + kA] = (kA < vl) ? a00 : MASK_VALUE;
    S[qA * LK + kB] = (kB < vl) ? a01 : MASK_VALUE;
    S[qB * LK + kA] = (kA < vl) ? a10 : MASK_VALUE;
    S[qB * LK + kB] = (kB < vl) ? a11 : MASK_VALUE;
}

// ---------------------------------------------------------------------------
// Softmax over axis=1 (QUERY axis) per (b, k) column — reference quirk.
// ---------------------------------------------------------------------------
__global__ void softmax_kernel() {
    const int b = blockIdx.y;
    const int tx = threadIdx.x & 31;
    const int ty = threadIdx.x >> 5;  // 0..7
    const int k = blockIdx.x * 32 + tx;
    float* S = g_S + b * LQ * LK;

    float vals[32];
    float m = -3.4e38f;
    #pragma unroll
    for (int i = 0; i < 32; i++) {
        vals[i] = S[(i * 8 + ty) * LK + k];
        m = fmaxf(m, vals[i]);
    }

    __shared__ float red[8][33];
    red[ty][tx] = m;
    __syncthreads();
    float M = red[0][tx];
    #pragma unroll
    for (int t = 1; t < 8; t++) M = fmaxf(M, red[t][tx]);
    __syncthreads();

    float s = 0.f;
    #pragma unroll
    for (int i = 0; i < 32; i++) {
        vals[i] = __expf(vals[i] - M);
        s += vals[i];
    }
    red[ty][tx] = s;
    __syncthreads();
    float SUM = 0.f;
    #pragma unroll
    for (int t = 0; t < 8; t++) SUM += red[t][tx];

    const float inv = 1.0f / SUM;
    #pragma unroll
    for (int i = 0; i < 32; i++)
        S[(i * 8 + ty) * LK + k] = vals[i] * inv;
}

// ---------------------------------------------------------------------------
// Output NN GEMM (tf32, R6 structure): out[b][q][d] = sum_k A[b][q][k]*V[b][k][d]
// CTA 32q x 32d, 4 warps (2x2), warp tile 16x16; V staged transposed [d][k].
// grid (8, 8, 8) = 512 blocks.
// ---------------------------------------------------------------------------
__global__ void __launch_bounds__(128) out_kernel(
    const float* __restrict__ Vv, float* __restrict__ out) {
    const int b = blockIdx.z;
    const int q0 = blockIdx.y * 32;
    const int d0 = blockIdx.x * 32;
    const int tid = threadIdx.x;
    const int lane = tid & 31;
    const int warp = tid >> 5;
    const int gid = lane >> 2;
    const int tig = lane & 3;
    const int wq = (warp & 1) * 16;
    const int wn = (warp >> 1) * 16;

    const float* A = g_S + b * LQ * LK;
    const float* V = Vv + b * LK * DV;

    __shared__ uint32_t As[2][32 * TS];
    __shared__ uint32_t Vs[2][32 * VS];

    int srow[2], sc4[2];
    #pragma unroll
    for (int j = 0; j < 2; j++) {
        int idx = tid + j * 128;
        srow[j] = idx >> 3;
        sc4[j]  = idx & 7;
    }

    float d[2][4] = {};

    float4 av[2], vv[2];
    #pragma unroll
    for (int j = 0; j < 2; j++) {
        av[j] = *(const float4*)&A[(q0 + srow[j]) * LK + sc4[j] * 4];
        vv[j] = *(const float4*)&V[srow[j] * DV + d0 + sc4[j] * 4];
    }

    for (int c = 0; c < 8; c++) {
        uint32_t* AB = As[c & 1];
        uint32_t* VB = Vs[c & 1];
        #pragma unroll
        for (int j = 0; j < 2; j++) {
            uint32_t* pa = &AB[srow[j] * TS + sc4[j] * 4];
            pa[0] = f2tf(av[j].x); pa[1] = f2tf(av[j].y);
            pa[2] = f2tf(av[j].z); pa[3] = f2tf(av[j].w);
            const int dc = sc4[j] * 4;
            VB[(dc + 0) * VS + srow[j]] = f2tf(vv[j].x);
            VB[(dc + 1) * VS + srow[j]] = f2tf(vv[j].y);
            VB[(dc + 2) * VS + srow[j]] = f2tf(vv[j].z);
            VB[(dc + 3) * VS + srow[j]] = f2tf(vv[j].w);
        }
        __syncthreads();

        if (c < 7) {
            const int k0 = (c + 1) * 32;
            #pragma unroll
            for (int j = 0; j < 2; j++) {
                av[j] = *(const float4*)&A[(q0 + srow[j]) * LK + k0 + sc4[j] * 4];
                vv[j] = *(const float4*)&V[(k0 + srow[j]) * DV + d0 + sc4[j] * 4];
            }
        }

        #pragma unroll
        for (int ks = 0; ks < 4; ks++) {
            const int kk = ks * 8;
            uint32_t a[4], bfr[2][2];
            const int r = wq + gid;
            a[0] = AB[r * TS + kk + tig];
            a[1] = AB[(r + 8) * TS + kk + tig];
            a[2] = AB[r * TS + kk + tig + 4];
            a[3] = AB[(r + 8) * TS + kk + tig + 4];
            #pragma unroll
            for (int jn = 0; jn < 2; jn++) {
                int n = wn + jn * 8 + gid;
                bfr[jn][0] = VB[n * VS + kk + tig];
                bfr[jn][1] = VB[n * VS + kk + tig + 4];
            }
            mma8(d[0], a, bfr[0]);
            mma8(d[1], a, bfr[1]);
        }
    }

    float* O = out + b * LQ * DV;
    #pragma unroll
    for (int jn = 0; jn < 2; jn++) {
        int row = q0 + wq + gid;
        int col = d0 + wn + jn * 8 + tig * 2;
        *(float2*)&O[row * DV + col] = make_float2(d[jn][0], d[jn][1]);
        *(float2*)&O[(row + 8) * DV + col] = make_float2(d[jn][2], d[jn][3]);
    }
}

extern "C" void kernel_launch(void* const* d_in, const int* in_sizes, int n_in,
                              void* d_out, int out_size) {
    const float* queries    = (const float*)d_in[0];
    const float* keyes      = (const float*)d_in[1];
    const float* values     = (const float*)d_in[2];
    const int*   valid_lens = (const int*)d_in[3];
    const float* W_q        = (const float*)d_in[4];
    const float* W_k        = (const float*)d_in[5];
    const float* W_v        = (const float*)d_in[6];
    float* out = (float*)d_out;

    proj_kernel<<<dim3(4, 32, 2), 128>>>(queries, W_q, keyes, W_k);
    scores_kernel<<<dim3(8, 8, 8), 256>>>(W_v, valid_lens);
    softmax_kernel<<<dim3(8, 8), 256>>>();
    out_kernel<<<dim3(8, 8, 8), 128>>>(values, out);
}